// round 3
// baseline (speedup 1.0000x reference)
#include <cuda_runtime.h>
#include <cstdint>
#include <cstddef>

// Problem constants
#define Bb 4
#define Hh 8
#define Ss 2048
#define Dd 64
#define BM 64
#define BN 64
#define PS 68            // smem row stride (floats): mult of 4 for float4 alignment
#define TEMP_INV 0.125f  // 1/TEMPERATURE

// scratch: per-row inverse softmax sum, [B*H*S]
__device__ float g_inv_rowsum[Bb * Hh * Ss];

__global__ __launch_bounds__(256) void attn_fused_kernel(
    const float* __restrict__ q, const float* __restrict__ k,
    const float* __restrict__ v, const float* __restrict__ dis,
    const int* __restrict__ mask,
    float* __restrict__ out, float* __restrict__ attn)
{
    extern __shared__ float sm[];
    float* Qs = sm;             // [Dd][PS], Qs[d][i] = q[i][d] / TEMPERATURE
    float* KP = sm + Dd * PS;   // phase 1: K^T[d][j]; phase 2: P^T[j][i]
    float* Vs = sm + 2 * Dd * PS;  // [j][PS] = v[j][d]

    const int tid = threadIdx.x;
    const int tx = tid & 15;      // key/dd tile coord (16)
    const int ty = tid >> 4;      // query tile coord (16)
    const int qt = blockIdx.x, h = blockIdx.y, b = blockIdx.z;
    const int q0 = qt * BM;

    const float* qb = q + (((size_t)(b * Hh + h)) * Ss + q0) * Dd;
    const float* kb = k + ((size_t)(b * Hh + h)) * Ss * Dd;
    const float* vb = v + ((size_t)(b * Hh + h)) * Ss * Dd;
    const float* db = dis + (size_t)b * Ss * Ss + (size_t)q0 * Ss;
    const int* mb = mask + (size_t)b * Ss * Ss + (size_t)q0 * Ss;
    float* ab = attn + (((size_t)(b * Hh + h)) * Ss + q0) * Ss;

    // Load Q tile, transposed to d-major, pre-scaled by 1/TEMPERATURE
    for (int idx = tid; idx < BM * (Dd / 4); idx += 256) {
        int i = idx >> 4;
        int d4 = (idx & 15) << 2;
        float4 t = *(const float4*)(qb + (size_t)i * Dd + d4);
        Qs[(d4 + 0) * PS + i] = t.x * TEMP_INV;
        Qs[(d4 + 1) * PS + i] = t.y * TEMP_INV;
        Qs[(d4 + 2) * PS + i] = t.z * TEMP_INV;
        Qs[(d4 + 3) * PS + i] = t.w * TEMP_INV;
    }

    float o[4][4] = {};
    float rsum[4] = {0.f, 0.f, 0.f, 0.f};

    for (int nt = 0; nt < Ss / BN; nt++) {
        __syncthreads();  // guard KP/Vs overwrite vs previous iter's reads
        const int k0 = nt * BN;

        // Load K tile transposed to d-major; V tile direct (row-major)
        for (int idx = tid; idx < BN * (Dd / 4); idx += 256) {
            int j = idx >> 4;
            int d4 = (idx & 15) << 2;
            float4 t = *(const float4*)(kb + (size_t)(k0 + j) * Dd + d4);
            KP[(d4 + 0) * PS + j] = t.x;
            KP[(d4 + 1) * PS + j] = t.y;
            KP[(d4 + 2) * PS + j] = t.z;
            KP[(d4 + 3) * PS + j] = t.w;
            float4 tv = *(const float4*)(vb + (size_t)(k0 + j) * Dd + d4);
            *(float4*)(Vs + j * PS + d4) = tv;
        }
        __syncthreads();

        // QK^T: 4x4 microtile, loop over d
        float acc[4][4] = {};
        #pragma unroll 8
        for (int d = 0; d < Dd; d++) {
            float4 a4 = *(const float4*)(Qs + d * PS + (ty << 2));
            float4 b4 = *(const float4*)(KP + d * PS + (tx << 2));
            float av[4] = {a4.x, a4.y, a4.z, a4.w};
            float bv[4] = {b4.x, b4.y, b4.z, b4.w};
            #pragma unroll
            for (int r = 0; r < 4; r++)
                #pragma unroll
                for (int c = 0; c < 4; c++)
                    acc[r][c] += av[r] * bv[c];
        }

        // Elementwise: * inner_dis, mask -> 0, exp; write unnormalized p to attn
        #pragma unroll
        for (int r = 0; r < 4; r++) {
            int gi = (ty << 2) + r;
            size_t rowoff = (size_t)gi * Ss + k0 + (tx << 2);
            float4 dd = *(const float4*)(db + rowoff);
            int4 mm = *(const int4*)(mb + rowoff);
            float p0 = mm.x ? 0.f : __expf(acc[r][0] * dd.x);
            float p1 = mm.y ? 0.f : __expf(acc[r][1] * dd.y);
            float p2 = mm.z ? 0.f : __expf(acc[r][2] * dd.z);
            float p3 = mm.w ? 0.f : __expf(acc[r][3] * dd.w);
            rsum[r] += (p0 + p1) + (p2 + p3);
            *(float4*)(ab + rowoff) = make_float4(p0, p1, p2, p3);
            acc[r][0] = p0; acc[r][1] = p1; acc[r][2] = p2; acc[r][3] = p3;
        }

        __syncthreads();  // all QK reads of KP done before overwriting with P^T

        // Store P^T[j][i] into KP
        #pragma unroll
        for (int r = 0; r < 4; r++)
            #pragma unroll
            for (int c = 0; c < 4; c++)
                KP[((tx << 2) + c) * PS + (ty << 2) + r] = acc[r][c];
        __syncthreads();

        // O += P * V : 4x4 microtile over (query, dd), loop over j
        #pragma unroll 8
        for (int j = 0; j < BN; j++) {
            float4 p4 = *(const float4*)(KP + j * PS + (ty << 2));
            float4 v4 = *(const float4*)(Vs + j * PS + (tx << 2));
            float pv[4] = {p4.x, p4.y, p4.z, p4.w};
            float vv[4] = {v4.x, v4.y, v4.z, v4.w};
            #pragma unroll
            for (int r = 0; r < 4; r++)
                #pragma unroll
                for (int c = 0; c < 4; c++)
                    o[r][c] += pv[r] * vv[c];
        }
    }

    // Reduce rowsum across the 16 tx lanes (each 16-lane group shares rows)
    #pragma unroll
    for (int r = 0; r < 4; r++) {
        #pragma unroll
        for (int off = 1; off < 16; off <<= 1)
            rsum[r] += __shfl_xor_sync(0xffffffffu, rsum[r], off);
    }

    float inv[4];
    #pragma unroll
    for (int r = 0; r < 4; r++) inv[r] = 1.0f / rsum[r];

    if (tx == 0) {
        #pragma unroll
        for (int r = 0; r < 4; r++)
            g_inv_rowsum[((size_t)(b * Hh + h)) * Ss + q0 + (ty << 2) + r] = inv[r];
    }

    // Write normalized output
    #pragma unroll
    for (int r = 0; r < 4; r++) {
        int gi = (ty << 2) + r;
        float4 t = make_float4(o[r][0] * inv[r], o[r][1] * inv[r],
                               o[r][2] * inv[r], o[r][3] * inv[r]);
        *(float4*)(out + (((size_t)(b * Hh + h)) * Ss + q0 + gi) * Dd + (tx << 2)) = t;
    }
}

// Rescale attn by per-row 1/rowsum. One float4 per thread.
__global__ __launch_bounds__(256) void attn_norm_kernel(float* __restrict__ attn)
{
    size_t i = (size_t)blockIdx.x * blockDim.x + threadIdx.x;  // float4 index
    size_t row = i >> 9;  // 512 float4 per row of S=2048
    float inv = g_inv_rowsum[row];
    float4* a4 = (float4*)attn;
    float4 t = a4[i];
    t.x *= inv; t.y *= inv; t.z *= inv; t.w *= inv;
    a4[i] = t;
}

extern "C" void kernel_launch(void* const* d_in, const int* in_sizes, int n_in,
                              void* d_out, int out_size)
{
    const float* q = (const float*)d_in[0];
    const float* k = (const float*)d_in[1];
    const float* v = (const float*)d_in[2];
    const float* dis = (const float*)d_in[3];
    const int* mask = (const int*)d_in[4];

    // Output tuple (output, attn) flattened: [B*H*S*D | B*H*S*S]
    float* out = (float*)d_out;
    float* attn = (float*)d_out + (size_t)Bb * Hh * Ss * Dd;

    const int smem_bytes = 3 * Dd * PS * sizeof(float);  // 52224
    cudaFuncSetAttribute(attn_fused_kernel,
                         cudaFuncAttributeMaxDynamicSharedMemorySize, smem_bytes);

    dim3 grid(Ss / BM, Hh, Bb);
    attn_fused_kernel<<<grid, 256, smem_bytes>>>(q, k, v, dis, mask, out, attn);

    const size_t n4 = (size_t)Bb * Hh * Ss * Ss / 4;  // 33554432 float4s
    attn_norm_kernel<<<(unsigned)(n4 / 256), 256>>>(attn);
}

// round 4
// speedup vs baseline: 1.0013x; 1.0013x over previous
#include <cuda_runtime.h>
#include <cstdint>
#include <cstddef>

// Problem constants
#define Bb 4
#define Hh 8
#define Ss 2048
#define Dd 64
#define BM 64
#define BN 64
#define PS 68            // smem row stride (floats): mult of 4 for float4 alignment
#define TEMP_INV 0.125f  // 1/TEMPERATURE

// scratch: per-row inverse softmax sum, [B*H*S]
__device__ float g_inv_rowsum[Bb * Hh * Ss];

__global__ __launch_bounds__(256) void attn_fused_kernel(
    const float* __restrict__ q, const float* __restrict__ k,
    const float* __restrict__ v, const float* __restrict__ dis,
    const int* __restrict__ mask,
    float* __restrict__ out, float* __restrict__ attn)
{
    extern __shared__ float sm[];
    float* Qs = sm;             // [Dd][PS], Qs[d][i] = q[i][d] / TEMPERATURE
    float* KP = sm + Dd * PS;   // phase 1: K^T[d][j]; phase 2: P^T[j][i]
    float* Vs = sm + 2 * Dd * PS;  // [j][PS] = v[j][d]

    const int tid = threadIdx.x;
    const int tx = tid & 15;      // key/dd tile coord (16)
    const int ty = tid >> 4;      // query tile coord (16)
    const int qt = blockIdx.x, h = blockIdx.y, b = blockIdx.z;
    const int q0 = qt * BM;

    const float* qb = q + (((size_t)(b * Hh + h)) * Ss + q0) * Dd;
    const float* kb = k + ((size_t)(b * Hh + h)) * Ss * Dd;
    const float* vb = v + ((size_t)(b * Hh + h)) * Ss * Dd;
    const float* db = dis + (size_t)b * Ss * Ss + (size_t)q0 * Ss;
    const int* mb = mask + (size_t)b * Ss * Ss + (size_t)q0 * Ss;
    float* ab = attn + (((size_t)(b * Hh + h)) * Ss + q0) * Ss;

    // Load Q tile, transposed to d-major, pre-scaled by 1/TEMPERATURE
    for (int idx = tid; idx < BM * (Dd / 4); idx += 256) {
        int i = idx >> 4;
        int d4 = (idx & 15) << 2;
        float4 t = *(const float4*)(qb + (size_t)i * Dd + d4);
        Qs[(d4 + 0) * PS + i] = t.x * TEMP_INV;
        Qs[(d4 + 1) * PS + i] = t.y * TEMP_INV;
        Qs[(d4 + 2) * PS + i] = t.z * TEMP_INV;
        Qs[(d4 + 3) * PS + i] = t.w * TEMP_INV;
    }

    float o[4][4] = {};
    float rsum[4] = {0.f, 0.f, 0.f, 0.f};

    for (int nt = 0; nt < Ss / BN; nt++) {
        __syncthreads();  // guard KP/Vs overwrite vs previous iter's reads
        const int k0 = nt * BN;

        // Load K tile transposed to d-major; V tile direct (row-major)
        for (int idx = tid; idx < BN * (Dd / 4); idx += 256) {
            int j = idx >> 4;
            int d4 = (idx & 15) << 2;
            float4 t = *(const float4*)(kb + (size_t)(k0 + j) * Dd + d4);
            KP[(d4 + 0) * PS + j] = t.x;
            KP[(d4 + 1) * PS + j] = t.y;
            KP[(d4 + 2) * PS + j] = t.z;
            KP[(d4 + 3) * PS + j] = t.w;
            float4 tv = *(const float4*)(vb + (size_t)(k0 + j) * Dd + d4);
            *(float4*)(Vs + j * PS + d4) = tv;
        }
        __syncthreads();

        // QK^T: 4x4 microtile, loop over d
        float acc[4][4] = {};
        #pragma unroll 8
        for (int d = 0; d < Dd; d++) {
            float4 a4 = *(const float4*)(Qs + d * PS + (ty << 2));
            float4 b4 = *(const float4*)(KP + d * PS + (tx << 2));
            float av[4] = {a4.x, a4.y, a4.z, a4.w};
            float bv[4] = {b4.x, b4.y, b4.z, b4.w};
            #pragma unroll
            for (int r = 0; r < 4; r++)
                #pragma unroll
                for (int c = 0; c < 4; c++)
                    acc[r][c] += av[r] * bv[c];
        }

        // Elementwise: * inner_dis, mask -> 0, exp; write unnormalized p to attn
        #pragma unroll
        for (int r = 0; r < 4; r++) {
            int gi = (ty << 2) + r;
            size_t rowoff = (size_t)gi * Ss + k0 + (tx << 2);
            float4 dd = *(const float4*)(db + rowoff);
            int4 mm = *(const int4*)(mb + rowoff);
            float p0 = mm.x ? 0.f : __expf(acc[r][0] * dd.x);
            float p1 = mm.y ? 0.f : __expf(acc[r][1] * dd.y);
            float p2 = mm.z ? 0.f : __expf(acc[r][2] * dd.z);
            float p3 = mm.w ? 0.f : __expf(acc[r][3] * dd.w);
            rsum[r] += (p0 + p1) + (p2 + p3);
            *(float4*)(ab + rowoff) = make_float4(p0, p1, p2, p3);
            acc[r][0] = p0; acc[r][1] = p1; acc[r][2] = p2; acc[r][3] = p3;
        }

        __syncthreads();  // all QK reads of KP done before overwriting with P^T

        // Store P^T[j][i] into KP
        #pragma unroll
        for (int r = 0; r < 4; r++)
            #pragma unroll
            for (int c = 0; c < 4; c++)
                KP[((tx << 2) + c) * PS + (ty << 2) + r] = acc[r][c];
        __syncthreads();

        // O += P * V : 4x4 microtile over (query, dd), loop over j
        #pragma unroll 8
        for (int j = 0; j < BN; j++) {
            float4 p4 = *(const float4*)(KP + j * PS + (ty << 2));
            float4 v4 = *(const float4*)(Vs + j * PS + (tx << 2));
            float pv[4] = {p4.x, p4.y, p4.z, p4.w};
            float vv[4] = {v4.x, v4.y, v4.z, v4.w};
            #pragma unroll
            for (int r = 0; r < 4; r++)
                #pragma unroll
                for (int c = 0; c < 4; c++)
                    o[r][c] += pv[r] * vv[c];
        }
    }

    // Reduce rowsum across the 16 tx lanes (each 16-lane group shares rows)
    #pragma unroll
    for (int r = 0; r < 4; r++) {
        #pragma unroll
        for (int off = 1; off < 16; off <<= 1)
            rsum[r] += __shfl_xor_sync(0xffffffffu, rsum[r], off);
    }

    float inv[4];
    #pragma unroll
    for (int r = 0; r < 4; r++) inv[r] = 1.0f / rsum[r];

    if (tx == 0) {
        #pragma unroll
        for (int r = 0; r < 4; r++)
            g_inv_rowsum[((size_t)(b * Hh + h)) * Ss + q0 + (ty << 2) + r] = inv[r];
    }

    // Write normalized output
    #pragma unroll
    for (int r = 0; r < 4; r++) {
        int gi = (ty << 2) + r;
        float4 t = make_float4(o[r][0] * inv[r], o[r][1] * inv[r],
                               o[r][2] * inv[r], o[r][3] * inv[r]);
        *(float4*)(out + (((size_t)(b * Hh + h)) * Ss + q0 + gi) * Dd + (tx << 2)) = t;
    }
}

// Rescale attn by per-row 1/rowsum. One float4 per thread.
__global__ __launch_bounds__(256) void attn_norm_kernel(float* __restrict__ attn)
{
    size_t i = (size_t)blockIdx.x * blockDim.x + threadIdx.x;  // float4 index
    size_t row = i >> 9;  // 512 float4 per row of S=2048
    float inv = g_inv_rowsum[row];
    float4* a4 = (float4*)attn;
    float4 t = a4[i];
    t.x *= inv; t.y *= inv; t.z *= inv; t.w *= inv;
    a4[i] = t;
}

extern "C" void kernel_launch(void* const* d_in, const int* in_sizes, int n_in,
                              void* d_out, int out_size)
{
    const float* q = (const float*)d_in[0];
    const float* k = (const float*)d_in[1];
    const float* v = (const float*)d_in[2];
    const float* dis = (const float*)d_in[3];
    const int* mask = (const int*)d_in[4];

    // Output tuple (output, attn) flattened: [B*H*S*D | B*H*S*S]
    float* out = (float*)d_out;
    float* attn = (float*)d_out + (size_t)Bb * Hh * Ss * Dd;

    const int smem_bytes = 3 * Dd * PS * sizeof(float);  // 52224
    cudaFuncSetAttribute(attn_fused_kernel,
                         cudaFuncAttributeMaxDynamicSharedMemorySize, smem_bytes);

    dim3 grid(Ss / BM, Hh, Bb);
    attn_fused_kernel<<<grid, 256, smem_bytes>>>(q, k, v, dis, mask, out, attn);

    const size_t n4 = (size_t)Bb * Hh * Ss * Ss / 4;  // 33554432 float4s
    attn_norm_kernel<<<(unsigned)(n4 / 256), 256>>>(attn);
}